// round 2
// baseline (speedup 1.0000x reference)
#include <cuda_runtime.h>
#include <cstdint>
#include <math.h>

#define B     64
#define LA    8
#define H     512
#define V     16384
#define SS    316       // PREF+PROF+STATE+CTX+REL = 10+10+10+256+30
#define CTXN  256
#define NROWS (B*LA)    // 512
#define SCALE 0.04419417382415922f   // 512^-0.5

// ---------------- device scratch (no allocations allowed) ----------------
__device__ __align__(16) float g_gen_exp[(size_t)NROWS * V];   // exp(gen logits)
__device__ float g_copy_exp[NROWS * SS];                       // exp(copy logits), 0 if masked
__device__ float g_rowsum[NROWS];                              // softmax denominators

// ---------------- K0: zero row sums -------------------------------------
__global__ void k0_zero() {
    int i = blockIdx.x * blockDim.x + threadIdx.x;
    if (i < NROWS) g_rowsum[i] = 0.f;
}

// ---------------- K1: copy logits -> exp, masked, + row sums -------------
// One block per batch b. dec_out[b] (8x512) cached in smem; each warp handles
// source positions s strided by 8.
__global__ __launch_bounds__(256) void k1_copy(const float* __restrict__ dec,
                                               const float* __restrict__ srch,
                                               const int* __restrict__ mask) {
    __shared__ float dsm[LA][H];    // 16 KB
    __shared__ float lsum[LA];
    int b = blockIdx.x;
    int tid = threadIdx.x;
    for (int i = tid; i < LA * H; i += 256) dsm[i / H][i % H] = dec[b * LA * H + i];
    if (tid < LA) lsum[tid] = 0.f;
    __syncthreads();

    int warp = tid >> 5, lane = tid & 31;
    for (int s = warp; s < SS; s += 8) {
        int m = mask[b * SS + s];
        if (m == 0) {
            if (lane < LA) g_copy_exp[(b * LA + lane) * SS + s] = 0.f;
            continue;
        }
        float acc[LA];
        #pragma unroll
        for (int l = 0; l < LA; l++) acc[l] = 0.f;
        const float* vp = srch + ((size_t)b * SS + s) * H;
        for (int h = lane; h < H; h += 32) {
            float v = vp[h];
            #pragma unroll
            for (int l = 0; l < LA; l++) acc[l] += dsm[l][h] * v;
        }
        #pragma unroll
        for (int l = 0; l < LA; l++) {
            float a = acc[l];
            #pragma unroll
            for (int off = 16; off; off >>= 1) a += __shfl_xor_sync(0xffffffffu, a, off);
            if (lane == 0) {
                float e = __expf(a * SCALE);
                g_copy_exp[(b * LA + l) * SS + s] = e;
                atomicAdd(&lsum[l], e);
            }
        }
    }
    __syncthreads();
    if (tid < LA) atomicAdd(&g_rowsum[b * LA + tid], lsum[tid]);
}

// ---------------- K2: gen GEMM + exp + row-sum epilogue ------------------
// C[512,16384] = A[512,512] x W[512,16384]; 128x128 tile, BK=16, 256 threads,
// 8x8 microtile using packed fma.rn.f32x2 (2 FLOP/inst -> full fp32 rate).
#define BK 16
__global__ __launch_bounds__(256) void k2_gemm(const float* __restrict__ A,
                                               const float* __restrict__ W,
                                               const float* __restrict__ bias) {
    __shared__ float As[BK][128];
    __shared__ float Ws[BK][128];
    __shared__ float red[16][128];

    int tid = threadIdx.x;
    int bx = blockIdx.x, by = blockIdx.y;
    int tm = tid >> 4, tn = tid & 15;   // 16x16 thread grid, 8x8 micro

    unsigned long long c2[8][4];
    #pragma unroll
    for (int i = 0; i < 8; i++)
        #pragma unroll
        for (int j = 0; j < 4; j++) c2[i][j] = 0ull;

    int arow = tid >> 2;     // 0..63
    int akq  = tid & 3;      // 0..3
    int wkr  = tid >> 5;     // 0..7
    int wnq  = tid & 31;     // 0..31
    int tq   = tn >> 2;      // swizzle phase for conflict-free LDS.64

    for (int kt = 0; kt < H; kt += BK) {
        #pragma unroll
        for (int it = 0; it < 2; it++) {
            int r = arow + it * 64;
            float4 a4 = *(const float4*)&A[(size_t)(by * 128 + r) * H + kt + akq * 4];
            As[akq * 4 + 0][r] = a4.x;
            As[akq * 4 + 1][r] = a4.y;
            As[akq * 4 + 2][r] = a4.z;
            As[akq * 4 + 3][r] = a4.w;
        }
        #pragma unroll
        for (int it = 0; it < 2; it++) {
            int kr = wkr + it * 8;
            float4 w4 = *(const float4*)&W[(size_t)(kt + kr) * V + bx * 128 + wnq * 4];
            *(float4*)&Ws[kr][wnq * 4] = w4;
        }
        __syncthreads();
        #pragma unroll
        for (int k = 0; k < BK; k++) {
            unsigned long long bvec[4];
            #pragma unroll
            for (int s = 0; s < 4; s++) {             // swizzled order: conflict-free
                int j2 = (s + tq) & 3;
                bvec[j2] = *(const unsigned long long*)&Ws[k][tn * 8 + j2 * 2];
            }
            float4 a0 = *(const float4*)&As[k][tm * 8];
            float4 a1 = *(const float4*)&As[k][tm * 8 + 4];
            float av[8] = {a0.x, a0.y, a0.z, a0.w, a1.x, a1.y, a1.z, a1.w};
            #pragma unroll
            for (int i = 0; i < 8; i++) {
                unsigned long long ad;
                asm("mov.b64 %0, {%1, %1};" : "=l"(ad) : "f"(av[i]));
                #pragma unroll
                for (int j2 = 0; j2 < 4; j2++)
                    asm("fma.rn.f32x2 %0, %1, %2, %0;"
                        : "+l"(c2[i][j2]) : "l"(ad), "l"(bvec[j2]));
            }
        }
        __syncthreads();
    }

    // epilogue: logits -> exp, store, partial row sums
    int nbase = bx * 128 + tn * 8;
    float bb[8];
    #pragma unroll
    for (int j = 0; j < 8; j++) bb[j] = bias[nbase + j];

    #pragma unroll
    for (int i = 0; i < 8; i++) {
        int r = by * 128 + tm * 8 + i;
        float e[8];
        float rs = 0.f;
        #pragma unroll
        for (int j2 = 0; j2 < 4; j2++) {
            union { unsigned long long u; float2 f; } cv;
            cv.u = c2[i][j2];
            float e0 = __expf((cv.f.x + bb[j2 * 2 + 0]) * SCALE);
            float e1 = __expf((cv.f.y + bb[j2 * 2 + 1]) * SCALE);
            e[j2 * 2 + 0] = e0;
            e[j2 * 2 + 1] = e1;
            rs += e0 + e1;
        }
        float4 s0 = make_float4(e[0], e[1], e[2], e[3]);
        float4 s1 = make_float4(e[4], e[5], e[6], e[7]);
        *(float4*)&g_gen_exp[(size_t)r * V + nbase]     = s0;
        *(float4*)&g_gen_exp[(size_t)r * V + nbase + 4] = s1;
        red[tn][tm * 8 + i] = rs;
    }
    __syncthreads();
    if (tid < 128) {
        float t = 0.f;
        #pragma unroll
        for (int j = 0; j < 16; j++) t += red[j][tid];
        atomicAdd(&g_rowsum[by * 128 + tid], t);
    }
}

// ---------------- K4: combine gen probs + dense one-hot einsums ----------
// Block = (v-chunk of 256, batch b). out = gen_exp*invZ + sum_p pc[p]*M[b,p,v]
__global__ __launch_bounds__(256) void k4_combine(const float* __restrict__ pv,
                                                  const float* __restrict__ lmat,
                                                  const float* __restrict__ tpm,
                                                  const float* __restrict__ rel,
                                                  float* __restrict__ out) {
    __shared__ float pc[60][LA];   // normalized copy probs for the 60 one-hot rows
    __shared__ float invZ[LA];
    int b = blockIdx.y;
    int tid = threadIdx.x;
    if (tid < LA) invZ[tid] = 1.f / g_rowsum[b * LA + tid];
    __syncthreads();
    if (tid < 60) {
        int src = (tid < 30) ? tid : tid + CTXN;   // skip the 256 ctx slots
        #pragma unroll
        for (int l = 0; l < LA; l++)
            pc[tid][l] = g_copy_exp[(b * LA + l) * SS + src] * invZ[l];
    }
    __syncthreads();

    int v = blockIdx.x * 256 + tid;
    float acc[LA];
    #pragma unroll
    for (int l = 0; l < LA; l++)
        acc[l] = g_gen_exp[(size_t)(b * LA + l) * V + v] * invZ[l];

    const float* pvb = pv   + (size_t)b * 10 * V + v;
    const float* lb  = lmat + (size_t)b * 10 * V + v;
    const float* tb  = tpm  + (size_t)b * 10 * V + v;
    const float* rb  = rel  + (size_t)b * 30 * V + v;
    #pragma unroll
    for (int p = 0; p < 10; p++) {
        float m0 = pvb[(size_t)p * V];
        float m1 = lb [(size_t)p * V];
        float m2 = tb [(size_t)p * V];
        #pragma unroll
        for (int l = 0; l < LA; l++)
            acc[l] += pc[p][l] * m0 + pc[10 + p][l] * m1 + pc[20 + p][l] * m2;
    }
    #pragma unroll
    for (int p = 0; p < 30; p++) {
        float m3 = rb[(size_t)p * V];
        #pragma unroll
        for (int l = 0; l < LA; l++) acc[l] += pc[30 + p][l] * m3;
    }
    #pragma unroll
    for (int l = 0; l < LA; l++)
        out[(size_t)(b * LA + l) * V + v] = acc[l];
}

// ---------------- K5: ctx scatter-add ------------------------------------
__global__ void k5_ctx(const int* __restrict__ ctx, const int* __restrict__ g2l,
                       float* __restrict__ out) {
    int b = blockIdx.x, c = threadIdx.x;   // 256 threads
    int tgt = g2l[ctx[b * CTXN + c]];
    #pragma unroll
    for (int l = 0; l < LA; l++) {
        float val = g_copy_exp[(b * LA + l) * SS + 30 + c] / g_rowsum[b * LA + l];
        atomicAdd(&out[(size_t)(b * LA + l) * V + tgt], val);
    }
}

// ---------------- launch --------------------------------------------------
extern "C" void kernel_launch(void* const* d_in, const int* in_sizes, int n_in,
                              void* d_out, int out_size) {
    const float* dec  = (const float*)d_in[0];   // [64,8,512]
    const float* srch = (const float*)d_in[1];   // [64,316,512]
    const int*   mask = (const int*)  d_in[2];   // [64,1,316]
    const float* pv   = (const float*)d_in[3];   // [64,10,16384]
    const float* lmat = (const float*)d_in[4];   // [64,10,16384]
    const float* tpm  = (const float*)d_in[5];   // [64,10,16384]
    const float* rel  = (const float*)d_in[6];   // [64,30,16384]
    const float* W    = (const float*)d_in[7];   // [512,16384]
    const float* bias = (const float*)d_in[8];   // [16384]
    const int*   ctx  = (const int*)  d_in[9];   // [64,256]
    const int*   g2l  = (const int*)  d_in[10];  // [50000]
    float* out = (float*)d_out;                  // [64,8,16384]

    k0_zero<<<2, 256>>>();
    k1_copy<<<B, 256>>>(dec, srch, mask);
    k2_gemm<<<dim3(V / 128, NROWS / 128), 256>>>(dec, W, bias);
    k4_combine<<<dim3(V / 256, B), 256>>>(pv, lmat, tpm, rel, out);
    k5_ctx<<<B, CTXN>>>(ctx, g2l, out);
}

// round 4
// speedup vs baseline: 7.7877x; 7.7877x over previous
#include <cuda_runtime.h>
#include <cuda_bf16.h>
#include <cstdint>
#include <math.h>

#define B     64
#define LA    8
#define H     512
#define V     16384
#define SS    316
#define CTXN  256
#define NROWS (B*LA)
#define SCALE 0.04419417382415922f   // 512^-0.5

// ---------------- device scratch ----------------
__device__ __align__(16) float g_gen_exp[(size_t)NROWS * V];
__device__ float g_copy_exp[NROWS * SS];
__device__ float g_rowsum[NROWS];
__device__ __align__(16) __nv_bfloat16 g_Abf[NROWS * H];       // dec bf16
__device__ __align__(16) __nv_bfloat16 g_Wt[(size_t)V * H];    // W^T bf16, K-major

// ---------------- helpers ----------------
__device__ __forceinline__ uint32_t smem_u32(const void* p) {
    uint32_t a;
    asm("{ .reg .u64 t; cvta.to.shared.u64 t, %1; cvt.u32.u64 %0, t; }" : "=r"(a) : "l"(p));
    return a;
}
__device__ __forceinline__ void ldmx4(uint32_t* r, uint32_t addr) {
    asm volatile("ldmatrix.sync.aligned.m8n8.x4.shared.b16 {%0,%1,%2,%3}, [%4];"
        : "=r"(r[0]), "=r"(r[1]), "=r"(r[2]), "=r"(r[3]) : "r"(addr));
}
__device__ __forceinline__ void mma16816(float* d, const uint32_t* a, uint32_t b0, uint32_t b1) {
    asm volatile("mma.sync.aligned.m16n8k16.row.col.f32.bf16.bf16.f32 "
        "{%0,%1,%2,%3}, {%4,%5,%6,%7}, {%8,%9}, {%0,%1,%2,%3};"
        : "+f"(d[0]), "+f"(d[1]), "+f"(d[2]), "+f"(d[3])
        : "r"(a[0]), "r"(a[1]), "r"(a[2]), "r"(a[3]), "r"(b0), "r"(b1));
}
__device__ __forceinline__ void cp_async16(uint32_t dst, const void* src) {
    asm volatile("cp.async.cg.shared.global [%0], [%1], 16;" :: "r"(dst), "l"(src));
}
#define CP_COMMIT() asm volatile("cp.async.commit_group;")
#define CP_WAIT(n)  asm volatile("cp.async.wait_group %0;" :: "n"(n))

// ---------------- K0: zero row sums ----------------
__global__ void k0_zero() {
    int i = blockIdx.x * blockDim.x + threadIdx.x;
    if (i < NROWS) g_rowsum[i] = 0.f;
}

// ---------------- Kc_A: dec fp32 -> bf16 ----------------
__global__ void kc_A(const float* __restrict__ dec) {
    int i = blockIdx.x * 256 + threadIdx.x;
    g_Abf[i] = __float2bfloat16(dec[i]);
}

// ---------------- Kc_W: W[K,V] -> Wt[V,K] bf16 ----------------
__global__ __launch_bounds__(256) void kc_W(const float* __restrict__ W) {
    __shared__ float t[32][33];
    int n0 = blockIdx.x * 32, k0 = blockIdx.y * 32;
    int tx = threadIdx.x & 31, ty = threadIdx.x >> 5;
    for (int i = ty; i < 32; i += 8)
        t[i][tx] = W[(size_t)(k0 + i) * V + n0 + tx];
    __syncthreads();
    for (int i = ty; i < 32; i += 8)
        g_Wt[(size_t)(n0 + i) * H + k0 + tx] = __float2bfloat16(t[tx][i]);
}

// ---------------- K1: copy logits -> exp + row sums ----------------
__global__ __launch_bounds__(256) void k1_copy(const float* __restrict__ dec,
                                               const float* __restrict__ srch,
                                               const int* __restrict__ mask) {
    __shared__ float dsm[LA][H];
    __shared__ float lsum[LA];
    int b = blockIdx.x;
    int tid = threadIdx.x;
    for (int i = tid; i < LA * H; i += 256) dsm[i / H][i % H] = dec[b * LA * H + i];
    if (tid < LA) lsum[tid] = 0.f;
    __syncthreads();

    int warp = tid >> 5, lane = tid & 31;
    for (int s = blockIdx.y * 8 + warp; s < SS; s += 32) {
        int m = mask[b * SS + s];
        if (m == 0) {
            if (lane < LA) g_copy_exp[(b * LA + lane) * SS + s] = 0.f;
            continue;
        }
        float acc[LA];
        #pragma unroll
        for (int l = 0; l < LA; l++) acc[l] = 0.f;
        const float* vp = srch + ((size_t)b * SS + s) * H;
        for (int h = lane; h < H; h += 32) {
            float v = vp[h];
            #pragma unroll
            for (int l = 0; l < LA; l++) acc[l] += dsm[l][h] * v;
        }
        #pragma unroll
        for (int l = 0; l < LA; l++) {
            float a = acc[l];
            #pragma unroll
            for (int off = 16; off; off >>= 1) a += __shfl_xor_sync(0xffffffffu, a, off);
            if (lane == 0) {
                float e = __expf(a * SCALE);
                g_copy_exp[(b * LA + l) * SS + s] = e;
                atomicAdd(&lsum[l], e);
            }
        }
    }
    __syncthreads();
    if (tid < LA) atomicAdd(&g_rowsum[b * LA + tid], lsum[tid]);
}

// ---------------- K2: warp-MMA bf16 GEMM + exp epilogue -------------------
// C[512,16384] = Abf[512,512] x Wt[16384,512]^T.  CTA 128x128, BK=32.
// 8 warps as 4(m) x 2(n); warp tile 32x64 = 2x8 m16n8k16 fragments.
// smem pitch 40 halfs (80B): r*80 mod 128 covers all 8 16B phases -> ldmatrix conflict-free.
#define PITCH 40
__global__ __launch_bounds__(256) void k2m(const float* __restrict__ bias) {
    __shared__ __align__(16) __nv_bfloat16 As[2][128 * PITCH];
    __shared__ __align__(16) __nv_bfloat16 Bs[2][128 * PITCH];

    int tid = threadIdx.x, wid = tid >> 5, lane = tid & 31;
    int bx = blockIdx.x, by = blockIdx.y;
    int wm = wid >> 1, wn = wid & 1;

    const __nv_bfloat16* Ag = g_Abf + (size_t)(by * 128) * H;
    const __nv_bfloat16* Bg = g_Wt + (size_t)(bx * 128) * H;

    float acc[2][8][4];
    #pragma unroll
    for (int i = 0; i < 2; i++)
        #pragma unroll
        for (int j = 0; j < 8; j++)
            #pragma unroll
            for (int k = 0; k < 4; k++) acc[i][j][k] = 0.f;

    // async tile load: 128 rows x 32 halfs (=4 x 16B chunks per row), A and B
    int ldrow = tid >> 2, ldc8 = (tid & 3) * 8;

    #define ISSUE(KT, BUF) do {                                                   \
        int _r0 = ldrow, _r1 = ldrow + 64;                                        \
        cp_async16(smem_u32(&As[BUF][_r0 * PITCH + ldc8]),                        \
                   Ag + (size_t)_r0 * H + (KT) * 32 + ldc8);                      \
        cp_async16(smem_u32(&As[BUF][_r1 * PITCH + ldc8]),                        \
                   Ag + (size_t)_r1 * H + (KT) * 32 + ldc8);                      \
        cp_async16(smem_u32(&Bs[BUF][_r0 * PITCH + ldc8]),                        \
                   Bg + (size_t)_r0 * H + (KT) * 32 + ldc8);                      \
        cp_async16(smem_u32(&Bs[BUF][_r1 * PITCH + ldc8]),                        \
                   Bg + (size_t)_r1 * H + (KT) * 32 + ldc8);                      \
        CP_COMMIT();                                                              \
    } while (0)

    ISSUE(0, 0);

    int g = lane >> 3, r = lane & 7;
    for (int kt = 0; kt < 16; kt++) {
        int cur = kt & 1;
        if (kt < 15) { ISSUE(kt + 1, cur ^ 1); CP_WAIT(1); }
        else         { CP_WAIT(0); }
        __syncthreads();

        #pragma unroll
        for (int kk = 0; kk < 2; kk++) {
            uint32_t afr[2][4];
            #pragma unroll
            for (int mt = 0; mt < 2; mt++) {
                int arow = wm * 32 + mt * 16 + (g & 1) * 8 + r;
                int acol = kk * 16 + (g >> 1) * 8;
                ldmx4(afr[mt], smem_u32(&As[cur][arow * PITCH + acol]));
            }
            uint32_t bfr[4][4];
            #pragma unroll
            for (int nq = 0; nq < 4; nq++) {
                int nrow = wn * 64 + nq * 16 + (g >> 1) * 8 + r;
                int ncol = kk * 16 + (g & 1) * 8;
                ldmx4(bfr[nq], smem_u32(&Bs[cur][nrow * PITCH + ncol]));
            }
            #pragma unroll
            for (int mt = 0; mt < 2; mt++)
                #pragma unroll
                for (int nt = 0; nt < 8; nt++)
                    mma16816(acc[mt][nt], afr[mt],
                             bfr[nt >> 1][(nt & 1) * 2], bfr[nt >> 1][(nt & 1) * 2 + 1]);
        }
        __syncthreads();
    }

    // ---- epilogue: bias + exp + store + rowsum atomics ----
    int r4 = lane >> 2, c2 = (lane & 3) * 2;
    #pragma unroll
    for (int mt = 0; mt < 2; mt++) {
        float rs0 = 0.f, rs1 = 0.f;
        #pragma unroll
        for (int nt = 0; nt < 8; nt++) {
            int col = bx * 128 + wn * 64 + nt * 8 + c2;
            float b0 = bias[col], b1 = bias[col + 1];
            int row0 = by * 128 + wm * 32 + mt * 16 + r4;
            float e0 = __expf((acc[mt][nt][0] + b0) * SCALE);
            float e1 = __expf((acc[mt][nt][1] + b1) * SCALE);
            *(float2*)&g_gen_exp[(size_t)row0 * V + col] = make_float2(e0, e1);
            rs0 += e0 + e1;
            float e2 = __expf((acc[mt][nt][2] + b0) * SCALE);
            float e3 = __expf((acc[mt][nt][3] + b1) * SCALE);
            *(float2*)&g_gen_exp[(size_t)(row0 + 8) * V + col] = make_float2(e2, e3);
            rs1 += e2 + e3;
        }
        #pragma unroll
        for (int off = 1; off < 4; off <<= 1) {
            rs0 += __shfl_xor_sync(0xffffffffu, rs0, off);
            rs1 += __shfl_xor_sync(0xffffffffu, rs1, off);
        }
        if ((lane & 3) == 0) {
            int row0 = by * 128 + wm * 32 + mt * 16 + r4;
            atomicAdd(&g_rowsum[row0], rs0);
            atomicAdd(&g_rowsum[row0 + 8], rs1);
        }
    }
}

// ---------------- K4: combine gen probs + dense one-hot einsums ----------
__global__ __launch_bounds__(256) void k4_combine(const float* __restrict__ pv,
                                                  const float* __restrict__ lmat,
                                                  const float* __restrict__ tpm,
                                                  const float* __restrict__ rel,
                                                  float* __restrict__ out) {
    __shared__ float pc[60][LA];
    __shared__ float invZ[LA];
    int b = blockIdx.y;
    int tid = threadIdx.x;
    if (tid < LA) invZ[tid] = 1.f / g_rowsum[b * LA + tid];
    __syncthreads();
    if (tid < 60) {
        int src = (tid < 30) ? tid : tid + CTXN;
        #pragma unroll
        for (int l = 0; l < LA; l++)
            pc[tid][l] = g_copy_exp[(b * LA + l) * SS + src] * invZ[l];
    }
    __syncthreads();

    int v = blockIdx.x * 256 + tid;
    float acc[LA];
    #pragma unroll
    for (int l = 0; l < LA; l++)
        acc[l] = g_gen_exp[(size_t)(b * LA + l) * V + v] * invZ[l];

    const float* pvb = pv   + (size_t)b * 10 * V + v;
    const float* lb  = lmat + (size_t)b * 10 * V + v;
    const float* tb  = tpm  + (size_t)b * 10 * V + v;
    const float* rb  = rel  + (size_t)b * 30 * V + v;
    #pragma unroll
    for (int p = 0; p < 10; p++) {
        float m0 = pvb[(size_t)p * V];
        float m1 = lb [(size_t)p * V];
        float m2 = tb [(size_t)p * V];
        #pragma unroll
        for (int l = 0; l < LA; l++)
            acc[l] += pc[p][l] * m0 + pc[10 + p][l] * m1 + pc[20 + p][l] * m2;
    }
    #pragma unroll
    for (int p = 0; p < 30; p++) {
        float m3 = rb[(size_t)p * V];
        #pragma unroll
        for (int l = 0; l < LA; l++) acc[l] += pc[30 + p][l] * m3;
    }
    #pragma unroll
    for (int l = 0; l < LA; l++)
        out[(size_t)(b * LA + l) * V + v] = acc[l];
}

// ---------------- K5: ctx scatter-add ------------------------------------
__global__ void k5_ctx(const int* __restrict__ ctx, const int* __restrict__ g2l,
                       float* __restrict__ out) {
    int b = blockIdx.x, c = threadIdx.x;
    int tgt = g2l[ctx[b * CTXN + c]];
    #pragma unroll
    for (int l = 0; l < LA; l++) {
        float val = g_copy_exp[(b * LA + l) * SS + 30 + c] / g_rowsum[b * LA + l];
        atomicAdd(&out[(size_t)(b * LA + l) * V + tgt], val);
    }
}

// ---------------- launch --------------------------------------------------
extern "C" void kernel_launch(void* const* d_in, const int* in_sizes, int n_in,
                              void* d_out, int out_size) {
    const float* dec  = (const float*)d_in[0];
    const float* srch = (const float*)d_in[1];
    const int*   mask = (const int*)  d_in[2];
    const float* pv   = (const float*)d_in[3];
    const float* lmat = (const float*)d_in[4];
    const float* tpm  = (const float*)d_in[5];
    const float* rel  = (const float*)d_in[6];
    const float* W    = (const float*)d_in[7];
    const float* bias = (const float*)d_in[8];
    const int*   ctx  = (const int*)  d_in[9];
    const int*   g2l  = (const int*)  d_in[10];
    float* out = (float*)d_out;

    k0_zero<<<2, 256>>>();
    kc_A<<<NROWS * H / 256, 256>>>(dec);
    kc_W<<<dim3(V / 32, H / 32), 256>>>(W);
    k1_copy<<<dim3(B, 4), 256>>>(dec, srch, mask);
    k2m<<<dim3(V / 128, NROWS / 128), 256>>>(bias);
    k4_combine<<<dim3(V / 256, B), 256>>>(pv, lmat, tpm, rel, out);
    k5_ctx<<<B, CTXN>>>(ctx, g2l, out);
}

// round 5
// speedup vs baseline: 8.6979x; 1.1169x over previous
#include <cuda_runtime.h>
#include <cuda_bf16.h>
#include <cstdint>
#include <math.h>

#define B     64
#define LA    8
#define H     512
#define V     16384
#define SS    316
#define CTXN  256
#define NROWS (B*LA)
#define SCALE 0.04419417382415922f   // 512^-0.5

// ---------------- device scratch ----------------
__device__ __align__(16) float g_gen_exp[(size_t)NROWS * V];
__device__ float g_copy_exp[NROWS * SS];
__device__ float g_rowsum[NROWS];
__device__ __align__(16) __nv_bfloat16 g_Abf[NROWS * H];       // dec bf16
__device__ __align__(16) __nv_bfloat16 g_Wt[(size_t)V * H];    // W^T bf16, K-major

// ---------------- helpers ----------------
__device__ __forceinline__ uint32_t smem_u32(const void* p) {
    uint32_t a;
    asm("{ .reg .u64 t; cvta.to.shared.u64 t, %1; cvt.u32.u64 %0, t; }" : "=r"(a) : "l"(p));
    return a;
}
__device__ __forceinline__ void ldmx4(uint32_t* r, uint32_t addr) {
    asm volatile("ldmatrix.sync.aligned.m8n8.x4.shared.b16 {%0,%1,%2,%3}, [%4];"
        : "=r"(r[0]), "=r"(r[1]), "=r"(r[2]), "=r"(r[3]) : "r"(addr));
}
__device__ __forceinline__ void mma16816(float* d, const uint32_t* a, uint32_t b0, uint32_t b1) {
    asm volatile("mma.sync.aligned.m16n8k16.row.col.f32.bf16.bf16.f32 "
        "{%0,%1,%2,%3}, {%4,%5,%6,%7}, {%8,%9}, {%0,%1,%2,%3};"
        : "+f"(d[0]), "+f"(d[1]), "+f"(d[2]), "+f"(d[3])
        : "r"(a[0]), "r"(a[1]), "r"(a[2]), "r"(a[3]), "r"(b0), "r"(b1));
}
__device__ __forceinline__ void cp_async16(uint32_t dst, const void* src) {
    asm volatile("cp.async.cg.shared.global [%0], [%1], 16;" :: "r"(dst), "l"(src));
}
#define CP_COMMIT() asm volatile("cp.async.commit_group;")
#define CP_WAIT(n)  asm volatile("cp.async.wait_group %0;" :: "n"(n))

__device__ __forceinline__ unsigned long long pack2(float x) {
    unsigned long long r;
    asm("mov.b64 %0, {%1, %1};" : "=l"(r) : "f"(x));
    return r;
}
__device__ __forceinline__ void fma2(unsigned long long& d, unsigned long long a,
                                     unsigned long long b) {
    asm("fma.rn.f32x2 %0, %1, %2, %0;" : "+l"(d) : "l"(a), "l"(b));
}
__device__ __forceinline__ unsigned long long mul2(unsigned long long a, unsigned long long b) {
    unsigned long long r;
    asm("mul.rn.f32x2 %0, %1, %2;" : "=l"(r) : "l"(a), "l"(b));
    return r;
}

// ---------------- Kc_A: dec fp32 -> bf16 (+ zero rowsums) ----------------
__global__ void kc_A(const float* __restrict__ dec) {
    int i = blockIdx.x * 256 + threadIdx.x;
    g_Abf[i] = __float2bfloat16(dec[i]);
    if (i < NROWS) g_rowsum[i] = 0.f;
}

// ---------------- Kc_W: W[K,V] -> Wt[V,K] bf16, bf16x2 stores -------------
__global__ __launch_bounds__(256) void kc_W(const float* __restrict__ W) {
    __shared__ float t[64][33];
    int n0 = blockIdx.x * 32, k0 = blockIdx.y * 64;
    int tx = threadIdx.x & 31, ty = threadIdx.x >> 5;
    for (int i = ty; i < 64; i += 8)
        t[i][tx] = W[(size_t)(k0 + i) * V + n0 + tx];
    __syncthreads();
    for (int i = ty; i < 32; i += 8) {
        __nv_bfloat162 h2;
        h2.x = __float2bfloat16(t[2 * tx][i]);
        h2.y = __float2bfloat16(t[2 * tx + 1][i]);
        *(__nv_bfloat162*)&g_Wt[(size_t)(n0 + i) * H + k0 + 2 * tx] = h2;
    }
}

// ---------------- K1: copy logits -> exp + row sums (thread per s) --------
#define K1_T 160
__global__ __launch_bounds__(K1_T) void k1_copy(const float* __restrict__ dec,
                                                const float* __restrict__ srch,
                                                const int* __restrict__ mask) {
    __shared__ float4 dsm[LA][H / 4];   // 16 KB, broadcast reads
    __shared__ float lsum[LA];
    int b = blockIdx.x;
    int tid = threadIdx.x;
    const float4* dg = (const float4*)(dec + (size_t)b * LA * H);
    for (int i = tid; i < LA * H / 4; i += K1_T)
        ((float4*)dsm)[i] = dg[i];
    if (tid < LA) lsum[tid] = 0.f;
    __syncthreads();

    int s = blockIdx.y * K1_T + tid;
    bool valid = (s < SS);
    int m = valid ? mask[b * SS + s] : 0;

    float acc[LA];
    #pragma unroll
    for (int l = 0; l < LA; l++) acc[l] = 0.f;

    if (m != 0) {
        const float4* vp = (const float4*)(srch + ((size_t)b * SS + s) * H);
        #pragma unroll 8
        for (int h4 = 0; h4 < H / 4; h4 += 2) {
            float4 v0 = vp[h4], v1 = vp[h4 + 1];
            #pragma unroll
            for (int l = 0; l < LA; l++) {
                float4 d0 = dsm[l][h4];
                acc[l] += d0.x * v0.x + d0.y * v0.y + d0.z * v0.z + d0.w * v0.w;
                float4 d1 = dsm[l][h4 + 1];
                acc[l] += d1.x * v1.x + d1.y * v1.y + d1.z * v1.z + d1.w * v1.w;
            }
        }
    }

    #pragma unroll
    for (int l = 0; l < LA; l++) {
        float e = (m != 0) ? __expf(acc[l] * SCALE) : 0.f;
        if (valid) g_copy_exp[(b * LA + l) * SS + s] = e;
        float r = e;
        #pragma unroll
        for (int off = 16; off; off >>= 1) r += __shfl_xor_sync(0xffffffffu, r, off);
        if ((tid & 31) == 0) atomicAdd(&lsum[l], r);
    }
    __syncthreads();
    if (tid < LA) atomicAdd(&g_rowsum[b * LA + tid], lsum[tid]);
}

// ---------------- K2: warp-MMA bf16 GEMM + exp epilogue -------------------
#define PITCH 40
__global__ __launch_bounds__(256) void k2m(const float* __restrict__ bias) {
    __shared__ __align__(16) __nv_bfloat16 As[2][128 * PITCH];
    __shared__ __align__(16) __nv_bfloat16 Bs[2][128 * PITCH];

    int tid = threadIdx.x, wid = tid >> 5, lane = tid & 31;
    int bx = blockIdx.x, by = blockIdx.y;
    int wm = wid >> 1, wn = wid & 1;

    const __nv_bfloat16* Ag = g_Abf + (size_t)(by * 128) * H;
    const __nv_bfloat16* Bg = g_Wt + (size_t)(bx * 128) * H;

    float acc[2][8][4];
    #pragma unroll
    for (int i = 0; i < 2; i++)
        #pragma unroll
        for (int j = 0; j < 8; j++)
            #pragma unroll
            for (int k = 0; k < 4; k++) acc[i][j][k] = 0.f;

    int ldrow = tid >> 2, ldc8 = (tid & 3) * 8;

    #define ISSUE(KT, BUF) do {                                                   \
        int _r0 = ldrow, _r1 = ldrow + 64;                                        \
        cp_async16(smem_u32(&As[BUF][_r0 * PITCH + ldc8]),                        \
                   Ag + (size_t)_r0 * H + (KT) * 32 + ldc8);                      \
        cp_async16(smem_u32(&As[BUF][_r1 * PITCH + ldc8]),                        \
                   Ag + (size_t)_r1 * H + (KT) * 32 + ldc8);                      \
        cp_async16(smem_u32(&Bs[BUF][_r0 * PITCH + ldc8]),                        \
                   Bg + (size_t)_r0 * H + (KT) * 32 + ldc8);                      \
        cp_async16(smem_u32(&Bs[BUF][_r1 * PITCH + ldc8]),                        \
                   Bg + (size_t)_r1 * H + (KT) * 32 + ldc8);                      \
        CP_COMMIT();                                                              \
    } while (0)

    ISSUE(0, 0);

    int g = lane >> 3, r = lane & 7;
    for (int kt = 0; kt < 16; kt++) {
        int cur = kt & 1;
        if (kt < 15) { ISSUE(kt + 1, cur ^ 1); CP_WAIT(1); }
        else         { CP_WAIT(0); }
        __syncthreads();

        #pragma unroll
        for (int kk = 0; kk < 2; kk++) {
            uint32_t afr[2][4];
            #pragma unroll
            for (int mt = 0; mt < 2; mt++) {
                int arow = wm * 32 + mt * 16 + (g & 1) * 8 + r;
                int acol = kk * 16 + (g >> 1) * 8;
                ldmx4(afr[mt], smem_u32(&As[cur][arow * PITCH + acol]));
            }
            uint32_t bfr[4][4];
            #pragma unroll
            for (int nq = 0; nq < 4; nq++) {
                int nrow = wn * 64 + nq * 16 + (g >> 1) * 8 + r;
                int ncol = kk * 16 + (g & 1) * 8;
                ldmx4(bfr[nq], smem_u32(&Bs[cur][nrow * PITCH + ncol]));
            }
            #pragma unroll
            for (int mt = 0; mt < 2; mt++)
                #pragma unroll
                for (int nt = 0; nt < 8; nt++)
                    mma16816(acc[mt][nt], afr[mt],
                             bfr[nt >> 1][(nt & 1) * 2], bfr[nt >> 1][(nt & 1) * 2 + 1]);
        }
        __syncthreads();
    }

    int r4 = lane >> 2, c2 = (lane & 3) * 2;
    #pragma unroll
    for (int mt = 0; mt < 2; mt++) {
        float rs0 = 0.f, rs1 = 0.f;
        #pragma unroll
        for (int nt = 0; nt < 8; nt++) {
            int col = bx * 128 + wn * 64 + nt * 8 + c2;
            float b0 = bias[col], b1 = bias[col + 1];
            int row0 = by * 128 + wm * 32 + mt * 16 + r4;
            float e0 = __expf((acc[mt][nt][0] + b0) * SCALE);
            float e1 = __expf((acc[mt][nt][1] + b1) * SCALE);
            *(float2*)&g_gen_exp[(size_t)row0 * V + col] = make_float2(e0, e1);
            rs0 += e0 + e1;
            float e2 = __expf((acc[mt][nt][2] + b0) * SCALE);
            float e3 = __expf((acc[mt][nt][3] + b1) * SCALE);
            *(float2*)&g_gen_exp[(size_t)(row0 + 8) * V + col] = make_float2(e2, e3);
            rs1 += e2 + e3;
        }
        #pragma unroll
        for (int off = 1; off < 4; off <<= 1) {
            rs0 += __shfl_xor_sync(0xffffffffu, rs0, off);
            rs1 += __shfl_xor_sync(0xffffffffu, rs1, off);
        }
        if ((lane & 3) == 0) {
            int row0 = by * 128 + wm * 32 + mt * 16 + r4;
            atomicAdd(&g_rowsum[row0], rs0);
            atomicAdd(&g_rowsum[row0 + 8], rs1);
        }
    }
}

// ---------------- K4: combine, float4 per thread + f32x2 FMA --------------
__global__ __launch_bounds__(256) void k4_combine(const float* __restrict__ pv,
                                                  const float* __restrict__ lmat,
                                                  const float* __restrict__ tpm,
                                                  const float* __restrict__ rel,
                                                  float* __restrict__ out) {
    __shared__ unsigned long long pc2[60][LA];   // packed {p,p}
    __shared__ unsigned long long iz2[LA];
    __shared__ float invZf[LA];
    int b = blockIdx.y;
    int tid = threadIdx.x;
    if (tid < LA) {
        float z = 1.f / g_rowsum[b * LA + tid];
        invZf[tid] = z;
        iz2[tid] = pack2(z);
    }
    __syncthreads();
    if (tid < 60) {
        int src = (tid < 30) ? tid : tid + CTXN;
        #pragma unroll
        for (int l = 0; l < LA; l++)
            pc2[tid][l] = pack2(g_copy_exp[(b * LA + l) * SS + src] * invZf[l]);
    }
    __syncthreads();

    int v = blockIdx.x * 1024 + tid * 4;
    unsigned long long acc[LA][2];
    #pragma unroll
    for (int l = 0; l < LA; l++) {
        ulonglong2 ge = *(const ulonglong2*)&g_gen_exp[(size_t)(b * LA + l) * V + v];
        acc[l][0] = mul2(ge.x, iz2[l]);
        acc[l][1] = mul2(ge.y, iz2[l]);
    }

    const float* pvb = pv   + (size_t)b * 10 * V + v;
    const float* lb  = lmat + (size_t)b * 10 * V + v;
    const float* tb  = tpm  + (size_t)b * 10 * V + v;
    const float* rb  = rel  + (size_t)b * 30 * V + v;
    #pragma unroll
    for (int p = 0; p < 10; p++) {
        ulonglong2 m0 = *(const ulonglong2*)&pvb[(size_t)p * V];
        ulonglong2 m1 = *(const ulonglong2*)&lb [(size_t)p * V];
        ulonglong2 m2 = *(const ulonglong2*)&tb [(size_t)p * V];
        #pragma unroll
        for (int l = 0; l < LA; l++) {
            fma2(acc[l][0], pc2[p][l], m0.x);      fma2(acc[l][1], pc2[p][l], m0.y);
            fma2(acc[l][0], pc2[10 + p][l], m1.x); fma2(acc[l][1], pc2[10 + p][l], m1.y);
            fma2(acc[l][0], pc2[20 + p][l], m2.x); fma2(acc[l][1], pc2[20 + p][l], m2.y);
        }
    }
    #pragma unroll
    for (int p = 0; p < 30; p++) {
        ulonglong2 m3 = *(const ulonglong2*)&rb[(size_t)p * V];
        #pragma unroll
        for (int l = 0; l < LA; l++) {
            fma2(acc[l][0], pc2[30 + p][l], m3.x);
            fma2(acc[l][1], pc2[30 + p][l], m3.y);
        }
    }
    #pragma unroll
    for (int l = 0; l < LA; l++) {
        ulonglong2 o;
        o.x = acc[l][0]; o.y = acc[l][1];
        *(ulonglong2*)&out[(size_t)(b * LA + l) * V + v] = o;
    }
}

// ---------------- K5: ctx scatter-add ------------------------------------
__global__ void k5_ctx(const int* __restrict__ ctx, const int* __restrict__ g2l,
                       float* __restrict__ out) {
    int b = blockIdx.x, c = threadIdx.x;
    int tgt = g2l[ctx[b * CTXN + c]];
    #pragma unroll
    for (int l = 0; l < LA; l++) {
        float val = g_copy_exp[(b * LA + l) * SS + 30 + c] / g_rowsum[b * LA + l];
        atomicAdd(&out[(size_t)(b * LA + l) * V + tgt], val);
    }
}

// ---------------- launch --------------------------------------------------
extern "C" void kernel_launch(void* const* d_in, const int* in_sizes, int n_in,
                              void* d_out, int out_size) {
    const float* dec  = (const float*)d_in[0];
    const float* srch = (const float*)d_in[1];
    const int*   mask = (const int*)  d_in[2];
    const float* pv   = (const float*)d_in[3];
    const float* lmat = (const float*)d_in[4];
    const float* tpm  = (const float*)d_in[5];
    const float* rel  = (const float*)d_in[6];
    const float* W    = (const float*)d_in[7];
    const float* bias = (const float*)d_in[8];
    const int*   ctx  = (const int*)  d_in[9];
    const int*   g2l  = (const int*)  d_in[10];
    float* out = (float*)d_out;

    kc_A<<<NROWS * H / 256, 256>>>(dec);
    kc_W<<<dim3(V / 32, H / 64), 256>>>(W);
    k1_copy<<<dim3(B, 2), K1_T>>>(dec, srch, mask);
    k2m<<<dim3(V / 128, NROWS / 128), 256>>>(bias);
    k4_combine<<<dim3(V / 1024, B), 256>>>(pv, lmat, tpm, rel, out);
    k5_ctx<<<B, CTXN>>>(ctx, g2l, out);
}

// round 6
// speedup vs baseline: 8.7379x; 1.0046x over previous
#include <cuda_runtime.h>
#include <cuda_bf16.h>
#include <cstdint>
#include <math.h>

#define B     64
#define LA    8
#define H     512
#define V     16384
#define SS    316
#define CTXN  256
#define NROWS (B*LA)
#define SCALE 0.04419417382415922f   // 512^-0.5

// ---------------- device scratch ----------------
__device__ __align__(16) float g_gen_exp[(size_t)NROWS * V];
__device__ float g_copy_exp[NROWS * SS];
__device__ float g_rowsum[NROWS];
__device__ __align__(16) __nv_bfloat16 g_Abf[NROWS * H];       // dec bf16
__device__ __align__(16) __nv_bfloat16 g_Wt[(size_t)V * H];    // W^T bf16, K-major

// ---------------- helpers ----------------
__device__ __forceinline__ uint32_t smem_u32(const void* p) {
    uint32_t a;
    asm("{ .reg .u64 t; cvta.to.shared.u64 t, %1; cvt.u32.u64 %0, t; }" : "=r"(a) : "l"(p));
    return a;
}
__device__ __forceinline__ void ldmx4(uint32_t* r, uint32_t addr) {
    asm volatile("ldmatrix.sync.aligned.m8n8.x4.shared.b16 {%0,%1,%2,%3}, [%4];"
        : "=r"(r[0]), "=r"(r[1]), "=r"(r[2]), "=r"(r[3]) : "r"(addr));
}
__device__ __forceinline__ void mma16816(float* d, const uint32_t* a, uint32_t b0, uint32_t b1) {
    asm volatile("mma.sync.aligned.m16n8k16.row.col.f32.bf16.bf16.f32 "
        "{%0,%1,%2,%3}, {%4,%5,%6,%7}, {%8,%9}, {%0,%1,%2,%3};"
        : "+f"(d[0]), "+f"(d[1]), "+f"(d[2]), "+f"(d[3])
        : "r"(a[0]), "r"(a[1]), "r"(a[2]), "r"(a[3]), "r"(b0), "r"(b1));
}
__device__ __forceinline__ void cp_async16(uint32_t dst, const void* src) {
    asm volatile("cp.async.cg.shared.global [%0], [%1], 16;" :: "r"(dst), "l"(src));
}
#define CP_COMMIT() asm volatile("cp.async.commit_group;")
#define CP_WAIT(n)  asm volatile("cp.async.wait_group %0;" :: "n"(n))

__device__ __forceinline__ unsigned long long pack2(float x) {
    unsigned long long r;
    asm("mov.b64 %0, {%1, %1};" : "=l"(r) : "f"(x));
    return r;
}
__device__ __forceinline__ void fma2(unsigned long long& d, unsigned long long a,
                                     unsigned long long b) {
    asm("fma.rn.f32x2 %0, %1, %2, %0;" : "+l"(d) : "l"(a), "l"(b));
}
__device__ __forceinline__ unsigned long long mul2(unsigned long long a, unsigned long long b) {
    unsigned long long r;
    asm("mul.rn.f32x2 %0, %1, %2;" : "=l"(r) : "l"(a), "l"(b));
    return r;
}

// ---------------- Kc_A: dec fp32 -> bf16 (+ zero rowsums) ----------------
__global__ void kc_A(const float* __restrict__ dec) {
    int i = blockIdx.x * 256 + threadIdx.x;
    g_Abf[i] = __float2bfloat16(dec[i]);
    if (i < NROWS) g_rowsum[i] = 0.f;
}

// ---------------- Kc_W: W[K,V] -> Wt[V,K] bf16, bf16x2 stores -------------
__global__ __launch_bounds__(256) void kc_W(const float* __restrict__ W) {
    __shared__ float t[64][33];
    int n0 = blockIdx.x * 32, k0 = blockIdx.y * 64;
    int tx = threadIdx.x & 31, ty = threadIdx.x >> 5;
    for (int i = ty; i < 64; i += 8)
        t[i][tx] = W[(size_t)(k0 + i) * V + n0 + tx];
    __syncthreads();
    for (int i = ty; i < 32; i += 8) {
        __nv_bfloat162 h2;
        h2.x = __float2bfloat16(t[2 * tx][i]);
        h2.y = __float2bfloat16(t[2 * tx + 1][i]);
        *(__nv_bfloat162*)&g_Wt[(size_t)(n0 + i) * H + k0 + 2 * tx] = h2;
    }
}

// ---------------- K1: copy logits -> exp + row sums (thread per s) --------
#define K1_T 160
__global__ __launch_bounds__(K1_T) void k1_copy(const float* __restrict__ dec,
                                                const float* __restrict__ srch,
                                                const int* __restrict__ mask) {
    __shared__ float4 dsm[LA][H / 4];   // 16 KB, broadcast reads
    __shared__ float lsum[LA];
    int b = blockIdx.x;
    int tid = threadIdx.x;
    const float4* dg = (const float4*)(dec + (size_t)b * LA * H);
    for (int i = tid; i < LA * H / 4; i += K1_T)
        ((float4*)dsm)[i] = dg[i];
    if (tid < LA) lsum[tid] = 0.f;
    __syncthreads();

    int s = blockIdx.y * K1_T + tid;
    bool valid = (s < SS);
    int m = valid ? mask[b * SS + s] : 0;

    float acc[LA];
    #pragma unroll
    for (int l = 0; l < LA; l++) acc[l] = 0.f;

    if (m != 0) {
        const float4* vp = (const float4*)(srch + ((size_t)b * SS + s) * H);
        #pragma unroll 8
        for (int h4 = 0; h4 < H / 4; h4 += 2) {
            float4 v0 = vp[h4], v1 = vp[h4 + 1];
            #pragma unroll
            for (int l = 0; l < LA; l++) {
                float4 d0 = dsm[l][h4];
                acc[l] += d0.x * v0.x + d0.y * v0.y + d0.z * v0.z + d0.w * v0.w;
                float4 d1 = dsm[l][h4 + 1];
                acc[l] += d1.x * v1.x + d1.y * v1.y + d1.z * v1.z + d1.w * v1.w;
            }
        }
    }

    #pragma unroll
    for (int l = 0; l < LA; l++) {
        float e = (m != 0) ? __expf(acc[l] * SCALE) : 0.f;
        if (valid) g_copy_exp[(b * LA + l) * SS + s] = e;
        float r = e;
        #pragma unroll
        for (int off = 16; off; off >>= 1) r += __shfl_xor_sync(0xffffffffu, r, off);
        if ((tid & 31) == 0) atomicAdd(&lsum[l], r);
    }
    __syncthreads();
    if (tid < LA) atomicAdd(&g_rowsum[b * LA + tid], lsum[tid]);
}

// ---------------- K2: warp-MMA bf16 GEMM + exp epilogue -------------------
#define PITCH 40
__global__ __launch_bounds__(256) void k2m(const float* __restrict__ bias) {
    __shared__ __align__(16) __nv_bfloat16 As[2][128 * PITCH];
    __shared__ __align__(16) __nv_bfloat16 Bs[2][128 * PITCH];

    int tid = threadIdx.x, wid = tid >> 5, lane = tid & 31;
    int bx = blockIdx.x, by = blockIdx.y;
    int wm = wid >> 1, wn = wid & 1;

    const __nv_bfloat16* Ag = g_Abf + (size_t)(by * 128) * H;
    const __nv_bfloat16* Bg = g_Wt + (size_t)(bx * 128) * H;

    float acc[2][8][4];
    #pragma unroll
    for (int i = 0; i < 2; i++)
        #pragma unroll
        for (int j = 0; j < 8; j++)
            #pragma unroll
            for (int k = 0; k < 4; k++) acc[i][j][k] = 0.f;

    int ldrow = tid >> 2, ldc8 = (tid & 3) * 8;

    #define ISSUE(KT, BUF) do {                                                   \
        int _r0 = ldrow, _r1 = ldrow + 64;                                        \
        cp_async16(smem_u32(&As[BUF][_r0 * PITCH + ldc8]),                        \
                   Ag + (size_t)_r0 * H + (KT) * 32 + ldc8);                      \
        cp_async16(smem_u32(&As[BUF][_r1 * PITCH + ldc8]),                        \
                   Ag + (size_t)_r1 * H + (KT) * 32 + ldc8);                      \
        cp_async16(smem_u32(&Bs[BUF][_r0 * PITCH + ldc8]),                        \
                   Bg + (size_t)_r0 * H + (KT) * 32 + ldc8);                      \
        cp_async16(smem_u32(&Bs[BUF][_r1 * PITCH + ldc8]),                        \
                   Bg + (size_t)_r1 * H + (KT) * 32 + ldc8);                      \
        CP_COMMIT();                                                              \
    } while (0)

    ISSUE(0, 0);

    int g = lane >> 3, r = lane & 7;
    for (int kt = 0; kt < 16; kt++) {
        int cur = kt & 1;
        if (kt < 15) { ISSUE(kt + 1, cur ^ 1); CP_WAIT(1); }
        else         { CP_WAIT(0); }
        __syncthreads();

        #pragma unroll
        for (int kk = 0; kk < 2; kk++) {
            uint32_t afr[2][4];
            #pragma unroll
            for (int mt = 0; mt < 2; mt++) {
                int arow = wm * 32 + mt * 16 + (g & 1) * 8 + r;
                int acol = kk * 16 + (g >> 1) * 8;
                ldmx4(afr[mt], smem_u32(&As[cur][arow * PITCH + acol]));
            }
            uint32_t bfr[4][4];
            #pragma unroll
            for (int nq = 0; nq < 4; nq++) {
                int nrow = wn * 64 + nq * 16 + (g >> 1) * 8 + r;
                int ncol = kk * 16 + (g & 1) * 8;
                ldmx4(bfr[nq], smem_u32(&Bs[cur][nrow * PITCH + ncol]));
            }
            #pragma unroll
            for (int mt = 0; mt < 2; mt++)
                #pragma unroll
                for (int nt = 0; nt < 8; nt++)
                    mma16816(acc[mt][nt], afr[mt],
                             bfr[nt >> 1][(nt & 1) * 2], bfr[nt >> 1][(nt & 1) * 2 + 1]);
        }
        __syncthreads();
    }

    int r4 = lane >> 2, c2 = (lane & 3) * 2;
    #pragma unroll
    for (int mt = 0; mt < 2; mt++) {
        float rs0 = 0.f, rs1 = 0.f;
        #pragma unroll
        for (int nt = 0; nt < 8; nt++) {
            int col = bx * 128 + wn * 64 + nt * 8 + c2;
            float b0 = bias[col], b1 = bias[col + 1];
            int row0 = by * 128 + wm * 32 + mt * 16 + r4;
            float e0 = __expf((acc[mt][nt][0] + b0) * SCALE);
            float e1 = __expf((acc[mt][nt][1] + b1) * SCALE);
            *(float2*)&g_gen_exp[(size_t)row0 * V + col] = make_float2(e0, e1);
            rs0 += e0 + e1;
            float e2 = __expf((acc[mt][nt][2] + b0) * SCALE);
            float e3 = __expf((acc[mt][nt][3] + b1) * SCALE);
            *(float2*)&g_gen_exp[(size_t)(row0 + 8) * V + col] = make_float2(e2, e3);
            rs1 += e2 + e3;
        }
        #pragma unroll
        for (int off = 1; off < 4; off <<= 1) {
            rs0 += __shfl_xor_sync(0xffffffffu, rs0, off);
            rs1 += __shfl_xor_sync(0xffffffffu, rs1, off);
        }
        if ((lane & 3) == 0) {
            int row0 = by * 128 + wm * 32 + mt * 16 + r4;
            atomicAdd(&g_rowsum[row0], rs0);
            atomicAdd(&g_rowsum[row0 + 8], rs1);
        }
    }
}

// ---------------- K4: combine, float4 per thread + f32x2 FMA --------------
__global__ __launch_bounds__(256) void k4_combine(const float* __restrict__ pv,
                                                  const float* __restrict__ lmat,
                                                  const float* __restrict__ tpm,
                                                  const float* __restrict__ rel,
                                                  float* __restrict__ out) {
    __shared__ unsigned long long pc2[60][LA];   // packed {p,p}
    __shared__ unsigned long long iz2[LA];
    __shared__ float invZf[LA];
    int b = blockIdx.y;
    int tid = threadIdx.x;
    if (tid < LA) {
        float z = 1.f / g_rowsum[b * LA + tid];
        invZf[tid] = z;
        iz2[tid] = pack2(z);
    }
    __syncthreads();
    if (tid < 60) {
        int src = (tid < 30) ? tid : tid + CTXN;
        #pragma unroll
        for (int l = 0; l < LA; l++)
            pc2[tid][l] = pack2(g_copy_exp[(b * LA + l) * SS + src] * invZf[l]);
    }
    __syncthreads();

    int v = blockIdx.x * 1024 + tid * 4;
    unsigned long long acc[LA][2];
    #pragma unroll
    for (int l = 0; l < LA; l++) {
        ulonglong2 ge = *(const ulonglong2*)&g_gen_exp[(size_t)(b * LA + l) * V + v];
        acc[l][0] = mul2(ge.x, iz2[l]);
        acc[l][1] = mul2(ge.y, iz2[l]);
    }

    const float* pvb = pv   + (size_t)b * 10 * V + v;
    const float* lb  = lmat + (size_t)b * 10 * V + v;
    const float* tb  = tpm  + (size_t)b * 10 * V + v;
    const float* rb  = rel  + (size_t)b * 30 * V + v;
    #pragma unroll
    for (int p = 0; p < 10; p++) {
        ulonglong2 m0 = *(const ulonglong2*)&pvb[(size_t)p * V];
        ulonglong2 m1 = *(const ulonglong2*)&lb [(size_t)p * V];
        ulonglong2 m2 = *(const ulonglong2*)&tb [(size_t)p * V];
        #pragma unroll
        for (int l = 0; l < LA; l++) {
            fma2(acc[l][0], pc2[p][l], m0.x);      fma2(acc[l][1], pc2[p][l], m0.y);
            fma2(acc[l][0], pc2[10 + p][l], m1.x); fma2(acc[l][1], pc2[10 + p][l], m1.y);
            fma2(acc[l][0], pc2[20 + p][l], m2.x); fma2(acc[l][1], pc2[20 + p][l], m2.y);
        }
    }
    #pragma unroll
    for (int p = 0; p < 30; p++) {
        ulonglong2 m3 = *(const ulonglong2*)&rb[(size_t)p * V];
        #pragma unroll
        for (int l = 0; l < LA; l++) {
            fma2(acc[l][0], pc2[30 + p][l], m3.x);
            fma2(acc[l][1], pc2[30 + p][l], m3.y);
        }
    }
    #pragma unroll
    for (int l = 0; l < LA; l++) {
        ulonglong2 o;
        o.x = acc[l][0]; o.y = acc[l][1];
        *(ulonglong2*)&out[(size_t)(b * LA + l) * V + v] = o;
    }
}

// ---------------- K5: ctx scatter-add ------------------------------------
__global__ void k5_ctx(const int* __restrict__ ctx, const int* __restrict__ g2l,
                       float* __restrict__ out) {
    int b = blockIdx.x, c = threadIdx.x;
    int tgt = g2l[ctx[b * CTXN + c]];
    #pragma unroll
    for (int l = 0; l < LA; l++) {
        float val = g_copy_exp[(b * LA + l) * SS + 30 + c] / g_rowsum[b * LA + l];
        atomicAdd(&out[(size_t)(b * LA + l) * V + tgt], val);
    }
}

// ---------------- launch --------------------------------------------------
extern "C" void kernel_launch(void* const* d_in, const int* in_sizes, int n_in,
                              void* d_out, int out_size) {
    const float* dec  = (const float*)d_in[0];
    const float* srch = (const float*)d_in[1];
    const int*   mask = (const int*)  d_in[2];
    const float* pv   = (const float*)d_in[3];
    const float* lmat = (const float*)d_in[4];
    const float* tpm  = (const float*)d_in[5];
    const float* rel  = (const float*)d_in[6];
    const float* W    = (const float*)d_in[7];
    const float* bias = (const float*)d_in[8];
    const int*   ctx  = (const int*)  d_in[9];
    const int*   g2l  = (const int*)  d_in[10];
    float* out = (float*)d_out;

    kc_A<<<NROWS * H / 256, 256>>>(dec);
    kc_W<<<dim3(V / 32, H / 64), 256>>>(W);
    k1_copy<<<dim3(B, 2), K1_T>>>(dec, srch, mask);
    k2m<<<dim3(V / 128, NROWS / 128), 256>>>(bias);
    k4_combine<<<dim3(V / 1024, B), 256>>>(pv, lmat, tpm, rel, out);
    k5_ctx<<<B, CTXN>>>(ctx, g2l, out);
}

// round 7
// speedup vs baseline: 8.9389x; 1.0230x over previous
#include <cuda_runtime.h>
#include <cuda_bf16.h>
#include <cstdint>
#include <math.h>

#define B     64
#define LA    8
#define H     512
#define V     16384
#define SS    316
#define CTXN  256
#define NROWS (B*LA)
#define SCALE 0.04419417382415922f   // 512^-0.5

// ---------------- device scratch ----------------
__device__ __align__(16) float g_gen_exp[(size_t)NROWS * V];
__device__ float g_copy_exp[NROWS * SS];
__device__ float g_rowsum[NROWS];
__device__ __align__(16) __nv_bfloat16 g_Abf[NROWS * H];       // dec bf16
__device__ __align__(16) __nv_bfloat16 g_Wt[(size_t)V * H];    // W^T bf16, K-major

// ---------------- helpers ----------------
__device__ __forceinline__ uint32_t smem_u32(const void* p) {
    uint32_t a;
    asm("{ .reg .u64 t; cvta.to.shared.u64 t, %1; cvt.u32.u64 %0, t; }" : "=r"(a) : "l"(p));
    return a;
}
__device__ __forceinline__ void ldmx4(uint32_t* r, uint32_t addr) {
    asm volatile("ldmatrix.sync.aligned.m8n8.x4.shared.b16 {%0,%1,%2,%3}, [%4];"
        : "=r"(r[0]), "=r"(r[1]), "=r"(r[2]), "=r"(r[3]) : "r"(addr));
}
__device__ __forceinline__ void mma16816(float* d, const uint32_t* a, uint32_t b0, uint32_t b1) {
    asm volatile("mma.sync.aligned.m16n8k16.row.col.f32.bf16.bf16.f32 "
        "{%0,%1,%2,%3}, {%4,%5,%6,%7}, {%8,%9}, {%0,%1,%2,%3};"
        : "+f"(d[0]), "+f"(d[1]), "+f"(d[2]), "+f"(d[3])
        : "r"(a[0]), "r"(a[1]), "r"(a[2]), "r"(a[3]), "r"(b0), "r"(b1));
}
__device__ __forceinline__ void cp_async16(uint32_t dst, const void* src) {
    asm volatile("cp.async.cg.shared.global [%0], [%1], 16;" :: "r"(dst), "l"(src));
}
#define CP_COMMIT() asm volatile("cp.async.commit_group;")
#define CP_WAIT(n)  asm volatile("cp.async.wait_group %0;" :: "n"(n))

// ---------------- Kc_A: dec fp32 -> bf16 (+ zero rowsums) ----------------
__global__ void kc_A(const float* __restrict__ dec) {
    int i = blockIdx.x * 256 + threadIdx.x;
    g_Abf[i] = __float2bfloat16(dec[i]);
    if (i < NROWS) g_rowsum[i] = 0.f;
}

// ---------------- Kc_W: W[K,V] -> Wt[V,K] bf16, bf16x2 stores -------------
__global__ __launch_bounds__(256) void kc_W(const float* __restrict__ W) {
    __shared__ float t[64][33];
    int n0 = blockIdx.x * 32, k0 = blockIdx.y * 64;
    int tx = threadIdx.x & 31, ty = threadIdx.x >> 5;
    for (int i = ty; i < 64; i += 8)
        t[i][tx] = W[(size_t)(k0 + i) * V + n0 + tx];
    __syncthreads();
    for (int i = ty; i < 32; i += 8) {
        __nv_bfloat162 h2;
        h2.x = __float2bfloat16(t[2 * tx][i]);
        h2.y = __float2bfloat16(t[2 * tx + 1][i]);
        *(__nv_bfloat162*)&g_Wt[(size_t)(n0 + i) * H + k0 + 2 * tx] = h2;
    }
}

// ---------------- K1: copy logits -> exp + row sums (thread per s) --------
#define K1_T 160
__global__ __launch_bounds__(K1_T) void k1_copy(const float* __restrict__ dec,
                                                const float* __restrict__ srch,
                                                const int* __restrict__ mask) {
    __shared__ float4 dsm[LA][H / 4];
    __shared__ float lsum[LA];
    int b = blockIdx.x;
    int tid = threadIdx.x;
    const float4* dg = (const float4*)(dec + (size_t)b * LA * H);
    for (int i = tid; i < LA * H / 4; i += K1_T)
        ((float4*)dsm)[i] = dg[i];
    if (tid < LA) lsum[tid] = 0.f;
    __syncthreads();

    int s = blockIdx.y * K1_T + tid;
    bool valid = (s < SS);
    int m = valid ? mask[b * SS + s] : 0;

    float acc[LA];
    #pragma unroll
    for (int l = 0; l < LA; l++) acc[l] = 0.f;

    if (m != 0) {
        const float4* vp = (const float4*)(srch + ((size_t)b * SS + s) * H);
        #pragma unroll 8
        for (int h4 = 0; h4 < H / 4; h4 += 2) {
            float4 v0 = vp[h4], v1 = vp[h4 + 1];
            #pragma unroll
            for (int l = 0; l < LA; l++) {
                float4 d0 = dsm[l][h4];
                acc[l] += d0.x * v0.x + d0.y * v0.y + d0.z * v0.z + d0.w * v0.w;
                float4 d1 = dsm[l][h4 + 1];
                acc[l] += d1.x * v1.x + d1.y * v1.y + d1.z * v1.z + d1.w * v1.w;
            }
        }
    }

    #pragma unroll
    for (int l = 0; l < LA; l++) {
        float e = (m != 0) ? __expf(acc[l] * SCALE) : 0.f;
        if (valid) g_copy_exp[(b * LA + l) * SS + s] = e;
        float r = e;
        #pragma unroll
        for (int off = 16; off; off >>= 1) r += __shfl_xor_sync(0xffffffffu, r, off);
        if ((tid & 31) == 0) atomicAdd(&lsum[l], r);
    }
    __syncthreads();
    if (tid < LA) atomicAdd(&g_rowsum[b * LA + tid], lsum[tid]);
}

// ---------------- K2: warp-MMA bf16 GEMM, 4-stage pipeline ----------------
#define PITCH 40
#define STG 4
#define TILE_HALFS (128 * PITCH)            // 5120 halfs = 10240 B per tile
#define K2_SMEM (STG * 2 * TILE_HALFS * 2)  // 81920 B
__global__ __launch_bounds__(256) void k2m(const float* __restrict__ bias) {
    extern __shared__ __align__(16) __nv_bfloat16 sm[];
    __nv_bfloat16* As = sm;                       // [STG][TILE_HALFS]
    __nv_bfloat16* Bs = sm + STG * TILE_HALFS;

    int tid = threadIdx.x, wid = tid >> 5, lane = tid & 31;
    int bx = blockIdx.x, by = blockIdx.y;
    int wm = wid >> 1, wn = wid & 1;

    const __nv_bfloat16* Ag = g_Abf + (size_t)(by * 128) * H;
    const __nv_bfloat16* Bg = g_Wt + (size_t)(bx * 128) * H;

    float acc[2][8][4];
    #pragma unroll
    for (int i = 0; i < 2; i++)
        #pragma unroll
        for (int j = 0; j < 8; j++)
            #pragma unroll
            for (int k = 0; k < 4; k++) acc[i][j][k] = 0.f;

    int ldrow = tid >> 2, ldc8 = (tid & 3) * 8;

    #define ISSUE(KT, BUF) do {                                                       \
        int _r0 = ldrow, _r1 = ldrow + 64;                                            \
        cp_async16(smem_u32(&As[(BUF) * TILE_HALFS + _r0 * PITCH + ldc8]),            \
                   Ag + (size_t)_r0 * H + (KT) * 32 + ldc8);                          \
        cp_async16(smem_u32(&As[(BUF) * TILE_HALFS + _r1 * PITCH + ldc8]),            \
                   Ag + (size_t)_r1 * H + (KT) * 32 + ldc8);                          \
        cp_async16(smem_u32(&Bs[(BUF) * TILE_HALFS + _r0 * PITCH + ldc8]),            \
                   Bg + (size_t)_r0 * H + (KT) * 32 + ldc8);                          \
        cp_async16(smem_u32(&Bs[(BUF) * TILE_HALFS + _r1 * PITCH + ldc8]),            \
                   Bg + (size_t)_r1 * H + (KT) * 32 + ldc8);                          \
        CP_COMMIT();                                                                   \
    } while (0)

    ISSUE(0, 0); ISSUE(1, 1); ISSUE(2, 2);

    int g = lane >> 3, r = lane & 7;
    uint32_t a0[2], b0[4];
    #pragma unroll
    for (int mt = 0; mt < 2; mt++)
        a0[mt] = smem_u32(&As[(wm * 32 + mt * 16 + (g & 1) * 8 + r) * PITCH + (g >> 1) * 8]);
    #pragma unroll
    for (int nq = 0; nq < 4; nq++)
        b0[nq] = smem_u32(&Bs[(wn * 64 + nq * 16 + (g >> 1) * 8 + r) * PITCH + (g & 1) * 8]);

    for (int kt = 0; kt < 16; kt++) {
        if (kt <= 13)      CP_WAIT(2);
        else if (kt == 14) CP_WAIT(1);
        else               CP_WAIT(0);
        __syncthreads();
        if (kt < 13) ISSUE(kt + 3, (kt + 3) & 3);

        uint32_t soff = (uint32_t)(kt & 3) * (TILE_HALFS * 2);
        #pragma unroll
        for (int kk = 0; kk < 2; kk++) {
            uint32_t ko = soff + kk * 32;
            uint32_t afr[2][4];
            #pragma unroll
            for (int mt = 0; mt < 2; mt++) ldmx4(afr[mt], a0[mt] + ko);
            uint32_t bfr[4][4];
            #pragma unroll
            for (int nq = 0; nq < 4; nq++) ldmx4(bfr[nq], b0[nq] + ko);
            #pragma unroll
            for (int mt = 0; mt < 2; mt++)
                #pragma unroll
                for (int nt = 0; nt < 8; nt++)
                    mma16816(acc[mt][nt], afr[mt],
                             bfr[nt >> 1][(nt & 1) * 2], bfr[nt >> 1][(nt & 1) * 2 + 1]);
        }
    }

    // epilogue: bias + exp (unnormalized) + rowsum atomics
    int r4 = lane >> 2, c2 = (lane & 3) * 2;
    #pragma unroll
    for (int mt = 0; mt < 2; mt++) {
        float rs0 = 0.f, rs1 = 0.f;
        #pragma unroll
        for (int nt = 0; nt < 8; nt++) {
            int col = bx * 128 + wn * 64 + nt * 8 + c2;
            float b0f = bias[col], b1f = bias[col + 1];
            int row0 = by * 128 + wm * 32 + mt * 16 + r4;
            float e0 = __expf((acc[mt][nt][0] + b0f) * SCALE);
            float e1 = __expf((acc[mt][nt][1] + b1f) * SCALE);
            *(float2*)&g_gen_exp[(size_t)row0 * V + col] = make_float2(e0, e1);
            rs0 += e0 + e1;
            float e2 = __expf((acc[mt][nt][2] + b0f) * SCALE);
            float e3 = __expf((acc[mt][nt][3] + b1f) * SCALE);
            *(float2*)&g_gen_exp[(size_t)(row0 + 8) * V + col] = make_float2(e2, e3);
            rs1 += e2 + e3;
        }
        #pragma unroll
        for (int off = 1; off < 4; off <<= 1) {
            rs0 += __shfl_xor_sync(0xffffffffu, rs0, off);
            rs1 += __shfl_xor_sync(0xffffffffu, rs1, off);
        }
        if ((lane & 3) == 0) {
            int row0 = by * 128 + wm * 32 + mt * 16 + r4;
            atomicAdd(&g_rowsum[row0], rs0);
            atomicAdd(&g_rowsum[row0 + 8], rs1);
        }
    }
}

// ---------------- K4n: out = gen_exp * invZ (one block per row) -----------
__global__ __launch_bounds__(256) void k4_norm(float* __restrict__ out) {
    int row = blockIdx.x;
    __shared__ float zs;
    if (threadIdx.x == 0) zs = 1.f / g_rowsum[row];
    __syncthreads();
    float z = zs;
    const float4* src = (const float4*)&g_gen_exp[(size_t)row * V];
    float4* dst = (float4*)&out[(size_t)row * V];
    #pragma unroll 4
    for (int i = threadIdx.x; i < V / 4; i += 256) {
        float4 v = src[i];
        v.x *= z; v.y *= z; v.z *= z; v.w *= z;
        dst[i] = v;
    }
}

// ---------------- K_scan: sparse scatter of one-hot einsums ---------------
// grid (4, 60, B). Streams the 4 matrices once; for every nonzero element
// M[b,p,v]=m, does out[b,l,v] += pc[p][l]*m — exact einsum for sparse M.
__global__ __launch_bounds__(256) void k_scan(const float* __restrict__ pv,
                                              const float* __restrict__ lmat,
                                              const float* __restrict__ tpm,
                                              const float* __restrict__ rel,
                                              float* __restrict__ out) {
    __shared__ float pcs[LA];
    int b = blockIdx.z, row = blockIdx.y, tid = threadIdx.x;

    const float* base;
    int p, np;
    if (row < 10)      { base = pv;   p = row;      np = 10; }
    else if (row < 20) { base = lmat; p = row - 10; np = 10; }
    else if (row < 30) { base = tpm;  p = row - 20; np = 10; }
    else               { base = rel;  p = row - 30; np = 30; }
    const float* mrow = base + ((size_t)b * np + p) * V;
    int src = (row < 30) ? row : row + CTXN;

    if (tid < LA)
        pcs[tid] = g_copy_exp[(b * LA + tid) * SS + src] / g_rowsum[b * LA + tid];
    __syncthreads();

    float* outb = out + (size_t)b * LA * V;
    float4 m[4];
    int i0 = blockIdx.x * 1024 + tid;
    #pragma unroll
    for (int q = 0; q < 4; q++)
        m[q] = *(const float4*)&mrow[(size_t)(i0 + q * 256) * 4];
    #pragma unroll
    for (int q = 0; q < 4; q++) {
        if (m[q].x != 0.f || m[q].y != 0.f || m[q].z != 0.f || m[q].w != 0.f) {
            int vb = (i0 + q * 256) * 4;
            float mv[4] = {m[q].x, m[q].y, m[q].z, m[q].w};
            #pragma unroll
            for (int c = 0; c < 4; c++) {
                if (mv[c] != 0.f) {
                    #pragma unroll
                    for (int l = 0; l < LA; l++)
                        atomicAdd(&outb[(size_t)l * V + vb + c], pcs[l] * mv[c]);
                }
            }
        }
    }
}

// ---------------- K5: ctx scatter-add ------------------------------------
__global__ void k5_ctx(const int* __restrict__ ctx, const int* __restrict__ g2l,
                       float* __restrict__ out) {
    int b = blockIdx.x, c = threadIdx.x;
    int tgt = g2l[ctx[b * CTXN + c]];
    #pragma unroll
    for (int l = 0; l < LA; l++) {
        float val = g_copy_exp[(b * LA + l) * SS + 30 + c] / g_rowsum[b * LA + l];
        atomicAdd(&out[(size_t)(b * LA + l) * V + tgt], val);
    }
}

// ---------------- launch --------------------------------------------------
extern "C" void kernel_launch(void* const* d_in, const int* in_sizes, int n_in,
                              void* d_out, int out_size) {
    const float* dec  = (const float*)d_in[0];
    const float* srch = (const float*)d_in[1];
    const int*   mask = (const int*)  d_in[2];
    const float* pv   = (const float*)d_in[3];
    const float* lmat = (const float*)d_in[4];
    const float* tpm  = (const float*)d_in[5];
    const float* rel  = (const float*)d_in[6];
    const float* W    = (const float*)d_in[7];
    const float* bias = (const float*)d_in[8];
    const int*   ctx  = (const int*)  d_in[9];
    const int*   g2l  = (const int*)  d_in[10];
    float* out = (float*)d_out;

    cudaFuncSetAttribute(k2m, cudaFuncAttributeMaxDynamicSharedMemorySize, K2_SMEM);

    kc_A<<<NROWS * H / 256, 256>>>(dec);
    kc_W<<<dim3(V / 32, H / 64), 256>>>(W);
    k1_copy<<<dim3(B, 2), K1_T>>>(dec, srch, mask);
    k2m<<<dim3(V / 128, NROWS / 128), 256, K2_SMEM>>>(bias);
    k4_norm<<<NROWS, 256>>>(out);
    k_scan<<<dim3(4, 60, B), 256>>>(pv, lmat, tpm, rel, out);
    k5_ctx<<<B, CTXN>>>(ctx, g2l, out);
}

// round 8
// speedup vs baseline: 9.6204x; 1.0762x over previous
#include <cuda_runtime.h>
#include <cuda_bf16.h>
#include <cstdint>
#include <math.h>

#define B     64
#define LA    8
#define H     512
#define V     16384
#define SS    316
#define CTXN  256
#define NROWS (B*LA)
#define SCALE 0.04419417382415922f   // 512^-0.5

// ---------------- device scratch ----------------
__device__ __align__(16) float g_gen_exp[(size_t)NROWS * V];
__device__ float g_copy_exp[NROWS * SS];
__device__ float g_rowsum[NROWS];
__device__ __align__(16) __nv_bfloat16 g_Abf[NROWS * H];       // dec bf16
__device__ __align__(16) __nv_bfloat16 g_Wt[(size_t)V * H];    // W^T bf16, K-major

// ---------------- helpers ----------------
__device__ __forceinline__ uint32_t smem_u32(const void* p) {
    uint32_t a;
    asm("{ .reg .u64 t; cvta.to.shared.u64 t, %1; cvt.u32.u64 %0, t; }" : "=r"(a) : "l"(p));
    return a;
}
__device__ __forceinline__ void ldmx4(uint32_t* r, uint32_t addr) {
    asm volatile("ldmatrix.sync.aligned.m8n8.x4.shared.b16 {%0,%1,%2,%3}, [%4];"
        : "=r"(r[0]), "=r"(r[1]), "=r"(r[2]), "=r"(r[3]) : "r"(addr));
}
__device__ __forceinline__ void mma16816(float* d, const uint32_t* a, uint32_t b0, uint32_t b1) {
    asm volatile("mma.sync.aligned.m16n8k16.row.col.f32.bf16.bf16.f32 "
        "{%0,%1,%2,%3}, {%4,%5,%6,%7}, {%8,%9}, {%0,%1,%2,%3};"
        : "+f"(d[0]), "+f"(d[1]), "+f"(d[2]), "+f"(d[3])
        : "r"(a[0]), "r"(a[1]), "r"(a[2]), "r"(a[3]), "r"(b0), "r"(b1));
}
__device__ __forceinline__ void cp_async16(uint32_t dst, const void* src) {
    asm volatile("cp.async.cg.shared.global [%0], [%1], 16;" :: "r"(dst), "l"(src));
}
#define CP_COMMIT() asm volatile("cp.async.commit_group;")
#define CP_WAIT(n)  asm volatile("cp.async.wait_group %0;" :: "n"(n))

__device__ __forceinline__ float4 ldcs4(const float* p) {
    float4 v;
    asm volatile("ld.global.cs.v4.f32 {%0,%1,%2,%3}, [%4];"
        : "=f"(v.x), "=f"(v.y), "=f"(v.z), "=f"(v.w) : "l"(p));
    return v;
}

// ---------------- Kc_A: dec fp32 -> bf16 (+ zero rowsums) ----------------
__global__ void kc_A(const float* __restrict__ dec) {
    int i = blockIdx.x * 256 + threadIdx.x;
    g_Abf[i] = __float2bfloat16(dec[i]);
    if (i < NROWS) g_rowsum[i] = 0.f;
}

// ---------------- Kc_W: W[K,V] -> Wt[V,K] bf16, bf16x2 stores -------------
__global__ __launch_bounds__(256) void kc_W(const float* __restrict__ W) {
    __shared__ float t[64][33];
    int n0 = blockIdx.x * 32, k0 = blockIdx.y * 64;
    int tx = threadIdx.x & 31, ty = threadIdx.x >> 5;
    for (int i = ty; i < 64; i += 8)
        t[i][tx] = W[(size_t)(k0 + i) * V + n0 + tx];
    __syncthreads();
    for (int i = ty; i < 32; i += 8) {
        __nv_bfloat162 h2;
        h2.x = __float2bfloat16(t[2 * tx][i]);
        h2.y = __float2bfloat16(t[2 * tx + 1][i]);
        *(__nv_bfloat162*)&g_Wt[(size_t)(n0 + i) * H + k0 + 2 * tx] = h2;
    }
}

// ---------------- K1: copy logits -> exp + row sums (thread per s) --------
#define K1_T 160
__global__ __launch_bounds__(K1_T) void k1_copy(const float* __restrict__ dec,
                                                const float* __restrict__ srch,
                                                const int* __restrict__ mask) {
    __shared__ float4 dsm[LA][H / 4];
    __shared__ float lsum[LA];
    int b = blockIdx.x;
    int tid = threadIdx.x;
    const float4* dg = (const float4*)(dec + (size_t)b * LA * H);
    for (int i = tid; i < LA * H / 4; i += K1_T)
        ((float4*)dsm)[i] = dg[i];
    if (tid < LA) lsum[tid] = 0.f;
    __syncthreads();

    int s = blockIdx.y * K1_T + tid;
    bool valid = (s < SS);
    int m = valid ? mask[b * SS + s] : 0;

    float acc[LA];
    #pragma unroll
    for (int l = 0; l < LA; l++) acc[l] = 0.f;

    if (m != 0) {
        const float4* vp = (const float4*)(srch + ((size_t)b * SS + s) * H);
        #pragma unroll 8
        for (int h4 = 0; h4 < H / 4; h4 += 2) {
            float4 v0 = vp[h4], v1 = vp[h4 + 1];
            #pragma unroll
            for (int l = 0; l < LA; l++) {
                float4 d0 = dsm[l][h4];
                acc[l] += d0.x * v0.x + d0.y * v0.y + d0.z * v0.z + d0.w * v0.w;
                float4 d1 = dsm[l][h4 + 1];
                acc[l] += d1.x * v1.x + d1.y * v1.y + d1.z * v1.z + d1.w * v1.w;
            }
        }
    }

    #pragma unroll
    for (int l = 0; l < LA; l++) {
        float e = (m != 0) ? __expf(acc[l] * SCALE) : 0.f;
        if (valid) g_copy_exp[(b * LA + l) * SS + s] = e;
        float r = e;
        #pragma unroll
        for (int off = 16; off; off >>= 1) r += __shfl_xor_sync(0xffffffffu, r, off);
        if ((tid & 31) == 0) atomicAdd(&lsum[l], r);
    }
    __syncthreads();
    if (tid < LA) atomicAdd(&g_rowsum[b * LA + tid], lsum[tid]);
}

// ---------------- K2: warp-MMA bf16 GEMM, warp tile 64x64 -----------------
// CTA 128x128, 128 threads (4 warps, 2m x 2n), BK=32, 3-stage cp.async.
#define PITCH 40
#define STG 3
#define TILE_HALFS (128 * PITCH)            // 5120 halfs = 10240 B per tile
#define K2_SMEM (STG * 2 * TILE_HALFS * 2)  // 61440 B
__global__ __launch_bounds__(128) void k2m(const float* __restrict__ bias) {
    extern __shared__ __align__(16) __nv_bfloat16 sm[];
    __nv_bfloat16* As = sm;                       // [STG][TILE_HALFS]
    __nv_bfloat16* Bs = sm + STG * TILE_HALFS;

    int tid = threadIdx.x, wid = tid >> 5, lane = tid & 31;
    int bx = blockIdx.x, by = blockIdx.y;
    int wm = wid >> 1, wn = wid & 1;

    const __nv_bfloat16* Ag = g_Abf + (size_t)(by * 128) * H;
    const __nv_bfloat16* Bg = g_Wt + (size_t)(bx * 128) * H;

    float acc[4][8][4];
    #pragma unroll
    for (int i = 0; i < 4; i++)
        #pragma unroll
        for (int j = 0; j < 8; j++)
            #pragma unroll
            for (int k = 0; k < 4; k++) acc[i][j][k] = 0.f;

    int ldr = tid >> 2, ldc8 = (tid & 3) * 8;   // rows ldr+32q, 4 chunks/row

    #define ISSUE(KT, BUF) do {                                                       \
        _Pragma("unroll")                                                              \
        for (int q = 0; q < 4; q++) {                                                  \
            int _r = ldr + 32 * q;                                                     \
            cp_async16(smem_u32(&As[(BUF) * TILE_HALFS + _r * PITCH + ldc8]),          \
                       Ag + (size_t)_r * H + (KT) * 32 + ldc8);                        \
            cp_async16(smem_u32(&Bs[(BUF) * TILE_HALFS + _r * PITCH + ldc8]),          \
                       Bg + (size_t)_r * H + (KT) * 32 + ldc8);                        \
        }                                                                              \
        CP_COMMIT();                                                                   \
    } while (0)

    ISSUE(0, 0); ISSUE(1, 1);

    int g = lane >> 3, r = lane & 7;
    uint32_t a0[4], b0[4];
    #pragma unroll
    for (int mt = 0; mt < 4; mt++)
        a0[mt] = smem_u32(&As[(wm * 64 + mt * 16 + (g & 1) * 8 + r) * PITCH + (g >> 1) * 8]);
    #pragma unroll
    for (int nq = 0; nq < 4; nq++)
        b0[nq] = smem_u32(&Bs[(wn * 64 + nq * 16 + (g >> 1) * 8 + r) * PITCH + (g & 1) * 8]);

    for (int kt = 0; kt < 16; kt++) {
        if (kt < 15) CP_WAIT(1); else CP_WAIT(0);
        __syncthreads();
        if (kt + 2 < 16) {
            int nb = (kt + 2) % STG;
            ISSUE(kt + 2, nb);
        }

        uint32_t soff = (uint32_t)(kt % STG) * (TILE_HALFS * 2);
        #pragma unroll
        for (int kk = 0; kk < 2; kk++) {
            uint32_t ko = soff + kk * 32;
            uint32_t afr[4][4];
            #pragma unroll
            for (int mt = 0; mt < 4; mt++) ldmx4(afr[mt], a0[mt] + ko);
            uint32_t bfr[4][4];
            #pragma unroll
            for (int nq = 0; nq < 4; nq++) ldmx4(bfr[nq], b0[nq] + ko);
            #pragma unroll
            for (int mt = 0; mt < 4; mt++)
                #pragma unroll
                for (int nt = 0; nt < 8; nt++)
                    mma16816(acc[mt][nt], afr[mt],
                             bfr[nt >> 1][(nt & 1) * 2], bfr[nt >> 1][(nt & 1) * 2 + 1]);
        }
    }

    // epilogue: bias + exp (unnormalized) + rowsum atomics
    int r4 = lane >> 2, c2 = (lane & 3) * 2;
    #pragma unroll
    for (int mt = 0; mt < 4; mt++) {
        float rs0 = 0.f, rs1 = 0.f;
        #pragma unroll
        for (int nt = 0; nt < 8; nt++) {
            int col = bx * 128 + wn * 64 + nt * 8 + c2;
            float b0f = bias[col], b1f = bias[col + 1];
            int row0 = by * 128 + wm * 64 + mt * 16 + r4;
            float e0 = __expf((acc[mt][nt][0] + b0f) * SCALE);
            float e1 = __expf((acc[mt][nt][1] + b1f) * SCALE);
            *(float2*)&g_gen_exp[(size_t)row0 * V + col] = make_float2(e0, e1);
            rs0 += e0 + e1;
            float e2 = __expf((acc[mt][nt][2] + b0f) * SCALE);
            float e3 = __expf((acc[mt][nt][3] + b1f) * SCALE);
            *(float2*)&g_gen_exp[(size_t)(row0 + 8) * V + col] = make_float2(e2, e3);
            rs1 += e2 + e3;
        }
        #pragma unroll
        for (int off = 1; off < 4; off <<= 1) {
            rs0 += __shfl_xor_sync(0xffffffffu, rs0, off);
            rs1 += __shfl_xor_sync(0xffffffffu, rs1, off);
        }
        if ((lane & 3) == 0) {
            int row0 = by * 128 + wm * 64 + mt * 16 + r4;
            atomicAdd(&g_rowsum[row0], rs0);
            atomicAdd(&g_rowsum[row0 + 8], rs1);
        }
    }
}

// ---------------- K4n: out = gen_exp * invZ (one block per row) -----------
__global__ __launch_bounds__(256) void k4_norm(float* __restrict__ out) {
    int row = blockIdx.x;
    __shared__ float zs;
    if (threadIdx.x == 0) zs = 1.f / g_rowsum[row];
    __syncthreads();
    float z = zs;
    const float* src = &g_gen_exp[(size_t)row * V];
    float4* dst = (float4*)&out[(size_t)row * V];
    #pragma unroll 4
    for (int i = threadIdx.x; i < V / 4; i += 256) {
        float4 v = ldcs4(src + i * 4);
        v.x *= z; v.y *= z; v.z *= z; v.w *= z;
        dst[i] = v;
    }
}

// ---------------- K_scan: sparse scatter of one-hot einsums ---------------
__global__ __launch_bounds__(256) void k_scan(const float* __restrict__ pv,
                                              const float* __restrict__ lmat,
                                              const float* __restrict__ tpm,
                                              const float* __restrict__ rel,
                                              float* __restrict__ out) {
    __shared__ float pcs[LA];
    int b = blockIdx.z, row = blockIdx.y, tid = threadIdx.x;

    const float* base;
    int p, np;
    if (row < 10)      { base = pv;   p = row;      np = 10; }
    else if (row < 20) { base = lmat; p = row - 10; np = 10; }
    else if (row < 30) { base = tpm;  p = row - 20; np = 10; }
    else               { base = rel;  p = row - 30; np = 30; }
    const float* mrow = base + ((size_t)b * np + p) * V;
    int src = (row < 30) ? row : row + CTXN;

    if (tid < LA)
        pcs[tid] = g_copy_exp[(b * LA + tid) * SS + src] / g_rowsum[b * LA + tid];
    __syncthreads();

    float* outb = out + (size_t)b * LA * V;
    float4 m[4];
    int i0 = blockIdx.x * 1024 + tid;
    #pragma unroll
    for (int q = 0; q < 4; q++)
        m[q] = ldcs4(&mrow[(size_t)(i0 + q * 256) * 4]);
    #pragma unroll
    for (int q = 0; q < 4; q++) {
        if (m[q].x != 0.f || m[q].y != 0.f || m[q].z != 0.f || m[q].w != 0.f) {
            int vb = (i0 + q * 256) * 4;
            float mv[4] = {m[q].x, m[q].y, m[q].z, m[q].w};
            #pragma unroll
            for (int c = 0; c < 4; c++) {
                if (mv[c] != 0.f) {
                    #pragma unroll
                    for (int l = 0; l < LA; l++)
                        atomicAdd(&outb[(size_t)l * V + vb + c], pcs[l] * mv[c]);
                }
            }
        }
    }
}

// ---------------- K5: ctx scatter-add ------------------------------------
__global__ void k5_ctx(const int* __restrict__ ctx, const int* __restrict__ g2l,
                       float* __restrict__ out) {
    int b = blockIdx.x, c = threadIdx.x;
    int tgt = g2l[ctx[b * CTXN + c]];
    #pragma unroll
    for (int l = 0; l < LA; l++) {
        float val = g_copy_exp[(b * LA + l) * SS + 30 + c] / g_rowsum[b * LA + l];
        atomicAdd(&out[(size_t)(b * LA + l) * V + tgt], val);
    }
}

// ---------------- launch --------------------------------------------------
extern "C" void kernel_launch(void* const* d_in, const int* in_sizes, int n_in,
                              void* d_out, int out_size) {
    const float* dec  = (const float*)d_in[0];
    const float* srch = (const float*)d_in[1];
    const int*   mask = (const int*)  d_in[2];
    const float* pv   = (const float*)d_in[3];
    const float* lmat = (const float*)d_in[4];
    const float* tpm  = (const float*)d_in[5];
    const float* rel  = (const float*)d_in[6];
    const float* W    = (const float*)d_in[7];
    const float* bias = (const float*)d_in[8];
    const int*   ctx  = (const int*)  d_in[9];
    const int*   g2l  = (const int*)  d_in[10];
    float* out = (float*)d_out;

    cudaFuncSetAttribute(k2m, cudaFuncAttributeMaxDynamicSharedMemorySize, K2_SMEM);

    kc_A<<<NROWS * H / 256, 256>>>(dec);
    kc_W<<<dim3(V / 32, H / 64), 256>>>(W);
    k1_copy<<<dim3(B, 2), K1_T>>>(dec, srch, mask);
    k2m<<<dim3(V / 128, NROWS / 128), 128, K2_SMEM>>>(bias);
    k4_norm<<<NROWS, 256>>>(out);
    k_scan<<<dim3(4, 60, B), 256>>>(pv, lmat, tpm, rel, out);
    k5_ctx<<<B, CTXN>>>(ctx, g2l, out);
}